// round 6
// baseline (speedup 1.0000x reference)
#include <cuda_runtime.h>
#include <math.h>
#include <stdint.h>

#define FULLMASK 0xFFFFFFFFu
#define SCALE 0.08838834764831845f

#define B_     32
#define H_     32
#define KVH_   8
#define G_     4       // H / KVH
#define D_     128
#define BS_    128
#define MAXB_  32
#define NSPLIT 16

#define TILE_   32          // positions per CTA-iteration
#define STAGES_ 2
#define ROWB_   512         // bytes per K or V row
#define STAGEB_ (2 * TILE_ * ROWB_)   // 32 KB: K rows then V rows

// Partial results scratch (allocation-free)
__device__ float g_pacc[B_ * KVH_ * NSPLIT * G_ * D_];   // 8 MB
__device__ float g_pl  [B_ * KVH_ * NSPLIT * G_];

// ---------------- Pass 1: split-KV, cp.async smem pipeline ----------------
__global__ __launch_bounds__(256, 2)
void paged_attn_split_kernel(const float* __restrict__ query,
                             const float* __restrict__ key_cache,
                             const float* __restrict__ value_cache,
                             const int*   __restrict__ block_tables,
                             const int*   __restrict__ context_lens)
{
    const int b     = blockIdx.x;
    const int kvh   = blockIdx.y;
    const int split = blockIdx.z;
    const int tid   = threadIdx.x;
    const int warp  = tid >> 5;
    const int lane  = tid & 31;

    extern __shared__ char dsm[];                 // [STAGES_][64 rows][512B]
    __shared__ int   s_bt[MAXB_];
    __shared__ float s_acc[8][G_][D_];            // 16 KB
    __shared__ float s_l[8][G_];

    uint32_t dsm_u32;
    asm("{ .reg .u64 t; cvta.to.shared.u64 t, %1; cvt.u32.u64 %0, t; }"
        : "=r"(dsm_u32) : "l"(dsm));

    const int ctx = context_lens[b];
    if (tid < MAXB_) s_bt[tid] = block_tables[b * MAXB_ + tid];
    __syncthreads();

    const int chunk = ((ctx + NSPLIT * TILE_ - 1) / (NSPLIT * TILE_)) * TILE_;
    const int start = split * chunk;
    const int end   = min(start + chunk, ctx);
    const int span  = end - start;
    const int niter = (span > 0) ? ((span + TILE_ - 1) / TILE_) : 0;

    // q for the 4 heads; lane owns d-slice [lane*4, lane*4+4)
    float q[G_][4];
#pragma unroll
    for (int h = 0; h < G_; h++) {
        const float4 qv = *reinterpret_cast<const float4*>(
            &query[((size_t)b * H_ + kvh * G_ + h) * D_ + lane * 4]);
        q[h][0] = qv.x * SCALE; q[h][1] = qv.y * SCALE;
        q[h][2] = qv.z * SCALE; q[h][3] = qv.w * SCALE;
    }

    float l[G_], acc[G_][4];
#pragma unroll
    for (int h = 0; h < G_; h++) {
        l[h] = 0.f;
        acc[h][0] = acc[h][1] = acc[h][2] = acc[h][3] = 0.f;
    }

    const bool b4 = (lane & 16) != 0;
    const bool b3 = (lane & 8) != 0;

    // Issue stage 'it' (32 K rows + 32 V rows) into buffer it % STAGES_.
    // 2048 16B chunks over 256 threads = 8 cp.async each; lanes of a warp take
    // consecutive chunks within a row -> fully coalesced 512B gmem segments.
    auto issue_stage = [&](int it) {
        const int p0 = start + it * TILE_;
        const uint32_t sbase = dsm_u32 + (uint32_t)(it % STAGES_) * STAGEB_;
#pragma unroll
        for (int k = 0; k < 8; k++) {
            const int i   = tid + k * 256;        // 0..2047
            const int row = i >> 5;               // 0..63 (0..31 K, 32..63 V)
            const int c   = i & 31;               // 16B chunk within row
            int p = p0 + (row & 31);
            p = min(p, end - 1);                  // clamp: stays in-table
            const int blk = s_bt[p >> 7];
            const size_t off = (((size_t)blk * BS_ + (p & 127)) * KVH_ + kvh) * D_ + c * 4;
            const float* src = ((row < TILE_) ? key_cache : value_cache) + off;
            const uint32_t dst = sbase + ((uint32_t)row << 9) + ((uint32_t)c << 4);
            asm volatile("cp.async.cg.shared.global [%0], [%1], 16;\n"
                         :: "r"(dst), "l"(src) : "memory");
        }
    };

    // Prime the pipeline: always commit STAGES_ groups (empty ones if short).
    if (niter > 0) issue_stage(0);
    asm volatile("cp.async.commit_group;\n" ::: "memory");
    if (niter > 1) issue_stage(1);
    asm volatile("cp.async.commit_group;\n" ::: "memory");

    for (int it = 0; it < niter; it++) {
        asm volatile("cp.async.wait_group 1;\n" ::: "memory");
        __syncthreads();                          // stage 'it' visible to all

        const uint32_t sbase = dsm_u32 + (uint32_t)(it % STAGES_) * STAGEB_;
        const int p0 = start + it * TILE_;

#pragma unroll
        for (int j = 0; j < 4; j++) {
            const int pos = p0 + warp * 4 + j;
            const bool valid = (pos < end);
            const int r = warp * 4 + j;

            float4 k;
            asm volatile("ld.shared.v4.f32 {%0,%1,%2,%3}, [%4];"
                         : "=f"(k.x), "=f"(k.y), "=f"(k.z), "=f"(k.w)
                         : "r"(sbase + ((uint32_t)r << 9) + ((uint32_t)lane << 4)));

            float p0h = q[0][0]*k.x + q[0][1]*k.y + q[0][2]*k.z + q[0][3]*k.w;
            float p1h = q[1][0]*k.x + q[1][1]*k.y + q[1][2]*k.z + q[1][3]*k.w;
            float p2h = q[2][0]*k.x + q[2][1]*k.y + q[2][2]*k.z + q[2][3]*k.w;
            float p3h = q[3][0]*k.x + q[3][1]*k.y + q[3][2]*k.z + q[3][3]*k.w;

            // Head-multiplexed butterfly: every lane ends with a complete head
            // sum (head = (bit4<<1)|bit3 of lane).
            float h0 = b4 ? p2h : p0h;
            float h1 = b4 ? p3h : p1h;
            float t0 = b4 ? p0h : p2h;
            float t1 = b4 ? p1h : p3h;
            h0 += __shfl_xor_sync(FULLMASK, t0, 16);
            h1 += __shfl_xor_sync(FULLMASK, t1, 16);
            float g  = b3 ? h1 : h0;
            float t2 = b3 ? h0 : h1;
            g += __shfl_xor_sync(FULLMASK, t2, 8);
            g += __shfl_xor_sync(FULLMASK, g, 4);
            g += __shfl_xor_sync(FULLMASK, g, 2);
            g += __shfl_xor_sync(FULLMASK, g, 1);

            const float w_local = __expf(g);      // one MUFU covers all 4 heads

            float4 v;
            asm volatile("ld.shared.v4.f32 {%0,%1,%2,%3}, [%4];"
                         : "=f"(v.x), "=f"(v.y), "=f"(v.z), "=f"(v.w)
                         : "r"(sbase + ((uint32_t)(TILE_ + r) << 9) + ((uint32_t)lane << 4)));

#pragma unroll
            for (int h = 0; h < G_; h++) {
                float w = __shfl_sync(FULLMASK, w_local, ((h >> 1) << 4) | ((h & 1) << 3));
                w = valid ? w : 0.f;
                l[h] += w;
                acc[h][0] += w * v.x;
                acc[h][1] += w * v.y;
                acc[h][2] += w * v.z;
                acc[h][3] += w * v.w;
            }
        }

        __syncthreads();                          // all readers done before reuse
        if (it + 2 < niter) issue_stage(it + 2);
        asm volatile("cp.async.commit_group;\n" ::: "memory");
    }

    // Per-warp partials -> shared
#pragma unroll
    for (int h = 0; h < G_; h++) {
        s_acc[warp][h][lane * 4 + 0] = acc[h][0];
        s_acc[warp][h][lane * 4 + 1] = acc[h][1];
        s_acc[warp][h][lane * 4 + 2] = acc[h][2];
        s_acc[warp][h][lane * 4 + 3] = acc[h][3];
    }
    if (lane < G_) s_l[warp][lane] = l[lane];
    __syncthreads();

    // Cross-warp combine (plain sums) -> scratch
    const size_t pbase = ((size_t)(b * KVH_ + kvh) * NSPLIT + split);
    float* pacc = g_pacc + pbase * (G_ * D_);

    for (int idx = tid; idx < G_ * D_; idx += 256) {
        const int h = idx >> 7;
        const int d = idx & 127;
        float sum = 0.f;
#pragma unroll
        for (int w = 0; w < 8; w++) sum += s_acc[w][h][d];
        pacc[idx] = sum;
        if (d == 0) {
            float L = 0.f;
#pragma unroll
            for (int w = 0; w < 8; w++) L += s_l[w][h];
            g_pl[pbase * G_ + h] = L;
        }
    }
}

// ---------------- Pass 2: combine splits (plain sums) ----------------
__global__ __launch_bounds__(512)
void paged_attn_reduce_kernel(float* __restrict__ out)
{
    const int b   = blockIdx.x;
    const int kvh = blockIdx.y;
    const int tid = threadIdx.x;

    __shared__ float s_l[NSPLIT][G_];
    const size_t base = (size_t)(b * KVH_ + kvh) * NSPLIT;
    if (tid < NSPLIT * G_) ((float*)s_l)[tid] = g_pl[base * G_ + tid];
    __syncthreads();

    const int h = tid >> 7;
    const int d = tid & 127;

    float sum = 0.f;
#pragma unroll
    for (int s = 0; s < NSPLIT; s++)
        sum += g_pacc[(base + s) * (G_ * D_) + h * D_ + d];

    float L = 0.f;
#pragma unroll
    for (int s = 0; s < NSPLIT; s++) L += s_l[s][h];

    out[((size_t)b * H_ + kvh * G_ + h) * D_ + d] = sum / L;
}

extern "C" void kernel_launch(void* const* d_in, const int* in_sizes, int n_in,
                              void* d_out, int out_size) {
    const float* query        = (const float*)d_in[0];
    const float* key_cache    = (const float*)d_in[1];
    const float* value_cache  = (const float*)d_in[2];
    const int*   block_tables = (const int*)d_in[3];
    const int*   context_lens = (const int*)d_in[4];
    float* out = (float*)d_out;

    const int dyn_smem = STAGES_ * STAGEB_;   // 64 KB
    cudaFuncSetAttribute(paged_attn_split_kernel,
                         cudaFuncAttributeMaxDynamicSharedMemorySize, dyn_smem);

    dim3 grid1(B_, KVH_, NSPLIT);
    paged_attn_split_kernel<<<grid1, 256, dyn_smem>>>(query, key_cache, value_cache,
                                                      block_tables, context_lens);
    dim3 grid2(B_, KVH_);
    paged_attn_reduce_kernel<<<grid2, 512>>>(out);
}